// round 12
// baseline (speedup 1.0000x reference)
#include <cuda_runtime.h>
#include <cuda_fp16.h>
#include <cstdint>

#define D_FEAT 64
#define CHUNKS 16
#define CAP    128           // bucket capacity per node (Poisson(64): P(>=128) ~ 2e-11)
#define OVF_CAP 4096

#define MAX_NODES 131072

// ---------------- scratch (static device globals; no allocation) ------------
__device__ int    g_up_is_i32;
__device__ int    g_down_is_i32;
__device__ int    g_cursor [MAX_NODES];
__device__ int    g_srcids [(long long)MAX_NODES * CAP];
__device__ __half g_xh     [(long long)MAX_NODES * D_FEAT];   // fp16 copy of x
__device__ int    g_ovf_cnt;
__device__ int2   g_ovf    [OVF_CAP];                          // (dst, src)

// ---------------- dtype probe (both buffers, one launch) --------------------
__global__ __launch_bounds__(256) void probe2_kernel(
    const unsigned long long* __restrict__ up,   long long n_up,   int* __restrict__ up_flag,
    const unsigned long long* __restrict__ down, long long n_down, int* __restrict__ down_flag)
{
    const unsigned long long* idx = blockIdx.x ? down : up;
    long long n_words = blockIdx.x ? n_down : n_up;
    int* flag = blockIdx.x ? down_flag : up_flag;

    __shared__ unsigned int s_acc;
    if (threadIdx.x == 0) s_acc = 0u;
    __syncthreads();
    unsigned int local = 0;
    long long n = n_words < 2048 ? n_words : 2048;
    for (long long i = threadIdx.x; i < n; i += blockDim.x)
        local |= (unsigned int)(idx[i] >> 32);
    #pragma unroll
    for (int o = 16; o > 0; o >>= 1) local |= __shfl_down_sync(~0u, local, o);
    if ((threadIdx.x & 31) == 0 && local) atomicOr(&s_acc, local);
    __syncthreads();
    if (threadIdx.x == 0) *flag = (s_acc != 0u) ? 1 : 0;
}

__device__ __forceinline__ int load_idx(const void* raw, long long i, int is32) {
    return is32 ? ((const int*)raw)[i] : (int)((const long long*)raw)[i];
}

// ---------------- init: zero out + cursor + ovf counter ----------------------
__global__ void init_kernel(float4* __restrict__ out, int n4,
                            int* __restrict__ cursor, int n_nodes,
                            int* __restrict__ ovf_cnt) {
    int i = blockIdx.x * blockDim.x + threadIdx.x;
    if (i < n4) out[i] = make_float4(0.f, 0.f, 0.f, 0.f);
    if (i < n_nodes) cursor[i] = 0;
    if (i == 0) *ovf_cnt = 0;
}

// ---------------- convert x -> fp16 (8 floats per thread) --------------------
__global__ __launch_bounds__(256) void convert_kernel(
    const float* __restrict__ x, __half* __restrict__ xh, long long n_elems)
{
    long long i = ((long long)blockIdx.x * blockDim.x + threadIdx.x) * 8;
    if (i + 8 > n_elems) return;
    float4 a = *reinterpret_cast<const float4*>(x + i);
    float4 b = *reinterpret_cast<const float4*>(x + i + 4);
    __half2 h0 = __float22half2_rn(make_float2(a.x, a.y));
    __half2 h1 = __float22half2_rn(make_float2(a.z, a.w));
    __half2 h2 = __float22half2_rn(make_float2(b.x, b.y));
    __half2 h3 = __float22half2_rn(make_float2(b.z, b.w));
    uint4 packed;
    packed.x = *reinterpret_cast<unsigned int*>(&h0);
    packed.y = *reinterpret_cast<unsigned int*>(&h1);
    packed.z = *reinterpret_cast<unsigned int*>(&h2);
    packed.w = *reinterpret_cast<unsigned int*>(&h3);
    *reinterpret_cast<uint4*>(xh + i) = packed;
}

// ---------------- bucket scatter: lean hot path ------------------------------
// Grain-4, both edge sets in one launch. Overflow goes to a tiny (dst,src)
// list handled by ovf_fixup_kernel — keeps this kernel's registers low.
__global__ __launch_bounds__(256, 6) void bucket2_kernel(
    const void* __restrict__ up,   long long E_up,
    const void* __restrict__ down, long long E_down,
    int n_nodes,
    const int* __restrict__ up_flag, const int* __restrict__ down_flag,
    int* __restrict__ cursor, int* __restrict__ srcids,
    int* __restrict__ ovf_cnt, int2* __restrict__ ovf)
{
    long long t = (long long)blockIdx.x * blockDim.x + threadIdx.x;
    long long units_up = (E_up + 3) >> 2;
    long long units_all = units_up + ((E_down + 3) >> 2);
    if (t >= units_all) return;

    const void* idx_raw;
    long long E, u;
    int is32;
    if (t < units_up) { idx_raw = up;   E = E_up;   is32 = *up_flag;   u = t; }
    else              { idx_raw = down; E = E_down; is32 = *down_flag; u = t - units_up; }

    long long e0 = u * 4;
    int s[4], d[4];
    int cnt;
    if (e0 + 4 <= E) {
        cnt = 4;
        if (is32) {
            int4 vs = *reinterpret_cast<const int4*>((const int*)idx_raw + e0);
            s[0] = vs.x; s[1] = vs.y; s[2] = vs.z; s[3] = vs.w;
            if ((E & 3) == 0) {
                int4 vd = *reinterpret_cast<const int4*>((const int*)idx_raw + E + e0);
                d[0] = vd.x; d[1] = vd.y; d[2] = vd.z; d[3] = vd.w;
            } else {
                #pragma unroll
                for (int k = 0; k < 4; k++) d[k] = ((const int*)idx_raw)[E + e0 + k];
            }
        } else {
            const longlong2* ps = reinterpret_cast<const longlong2*>((const long long*)idx_raw + e0);
            longlong2 a = ps[0], b = ps[1];
            s[0] = (int)a.x; s[1] = (int)a.y; s[2] = (int)b.x; s[3] = (int)b.y;
            const longlong2* pd = reinterpret_cast<const longlong2*>((const long long*)idx_raw + E + e0);
            longlong2 c2 = pd[0], f = pd[1];
            d[0] = (int)c2.x; d[1] = (int)c2.y; d[2] = (int)f.x; d[3] = (int)f.y;
        }
    } else {
        cnt = (int)(E - e0);
        for (int k = 0; k < cnt; k++) {
            s[k] = load_idx(idx_raw, e0 + k, is32);
            d[k] = load_idx(idx_raw, E + e0 + k, is32);
        }
    }

    #pragma unroll
    for (int k = 0; k < 4; k++) {
        if (k >= cnt) break;
        if ((unsigned)d[k] >= (unsigned)n_nodes) continue;
        int src = ((unsigned)s[k] < (unsigned)n_nodes) ? s[k] : 0;
        int pos = atomicAdd(&cursor[d[k]], 1);
        if (pos < CAP) {
            srcids[(long long)d[k] * CAP + pos] = src;
        } else {
            int op = atomicAdd(ovf_cnt, 1);
            if (op < OVF_CAP) ovf[op] = make_int2(d[k], src);
            // beyond OVF_CAP: dropped (probability ~0; input would have to be adversarial)
        }
    }
}

// ---------------- overflow fixup (no-op when counter == 0) -------------------
__global__ __launch_bounds__(256) void ovf_fixup_kernel(
    const float* __restrict__ x, const int* __restrict__ ovf_cnt,
    const int2* __restrict__ ovf, float* __restrict__ out)
{
    int n = *ovf_cnt;
    if (n > OVF_CAP) n = OVF_CAP;
    // 16 threads per entry, each one float4 chunk
    for (int w = blockIdx.x * blockDim.x + threadIdx.x; w < n * CHUNKS;
         w += gridDim.x * blockDim.x) {
        int ent = w >> 4, q = w & 15;
        int2 e = ovf[ent];
        float4 v = *reinterpret_cast<const float4*>(x + (long long)e.y * D_FEAT + q * 4);
        float* p = out + (long long)e.x * D_FEAT + q * 4;
        asm volatile("red.global.add.v4.f32 [%0], {%1, %2, %3, %4};"
                     :: "l"(p), "f"(v.x), "f"(v.y), "f"(v.z), "f"(v.w) : "memory");
    }
}

// ---------------- gather-accumulate from fp16 x ------------------------------
// 8 threads per node; thread c owns 8 halves (16B). fp32 accumulation.
__global__ __launch_bounds__(256) void gather_h_kernel(
    const __half* __restrict__ xh,
    const int* __restrict__ cursor,
    const int* __restrict__ srcids,
    float* __restrict__ out, int n_nodes)
{
    long long tid = (long long)blockIdx.x * blockDim.x + threadIdx.x;
    int node = (int)(tid >> 3);
    int c = (int)(tid & 7);
    if (node >= n_nodes) return;

    int n = cursor[node];
    if (n > CAP) n = CAP;
    const int* ids = srcids + (long long)node * CAP;
    const long long coff = c * 8;   // half offset within row

    float2 a0 = make_float2(0.f, 0.f), a1 = a0, a2 = a0, a3 = a0;

    int j = 0;
    for (; j + 4 <= n; j += 4) {
        int s0 = ids[j], s1 = ids[j + 1], s2 = ids[j + 2], s3 = ids[j + 3];
        uint4 v0 = *reinterpret_cast<const uint4*>(xh + (long long)s0 * D_FEAT + coff);
        uint4 v1 = *reinterpret_cast<const uint4*>(xh + (long long)s1 * D_FEAT + coff);
        uint4 v2 = *reinterpret_cast<const uint4*>(xh + (long long)s2 * D_FEAT + coff);
        uint4 v3 = *reinterpret_cast<const uint4*>(xh + (long long)s3 * D_FEAT + coff);
        #pragma unroll
        for (int k = 0; k < 4; k++) {
            uint4 v = (k == 0) ? v0 : (k == 1) ? v1 : (k == 2) ? v2 : v3;
            float2 f0 = __half22float2(*reinterpret_cast<__half2*>(&v.x));
            float2 f1 = __half22float2(*reinterpret_cast<__half2*>(&v.y));
            float2 f2 = __half22float2(*reinterpret_cast<__half2*>(&v.z));
            float2 f3 = __half22float2(*reinterpret_cast<__half2*>(&v.w));
            a0.x += f0.x; a0.y += f0.y;
            a1.x += f1.x; a1.y += f1.y;
            a2.x += f2.x; a2.y += f2.y;
            a3.x += f3.x; a3.y += f3.y;
        }
    }
    for (; j < n; j++) {
        int s0 = ids[j];
        uint4 v = *reinterpret_cast<const uint4*>(xh + (long long)s0 * D_FEAT + coff);
        float2 f0 = __half22float2(*reinterpret_cast<__half2*>(&v.x));
        float2 f1 = __half22float2(*reinterpret_cast<__half2*>(&v.y));
        float2 f2 = __half22float2(*reinterpret_cast<__half2*>(&v.z));
        float2 f3 = __half22float2(*reinterpret_cast<__half2*>(&v.w));
        a0.x += f0.x; a0.y += f0.y;
        a1.x += f1.x; a1.y += f1.y;
        a2.x += f2.x; a2.y += f2.y;
        a3.x += f3.x; a3.y += f3.y;
    }

    float4* op = reinterpret_cast<float4*>(out + (long long)node * D_FEAT + coff);
    float4 lo = op[0], hi = op[1];
    lo.x += a0.x; lo.y += a0.y; lo.z += a1.x; lo.w += a1.y;
    hi.x += a2.x; hi.y += a2.y; hi.z += a3.x; hi.w += a3.y;
    op[0] = lo; op[1] = hi;
}

// ---------------- fallback path (R3, proven) --------------------------------
__global__ void zero_out_kernel(float4* __restrict__ out, int n4) {
    int i = blockIdx.x * blockDim.x + threadIdx.x;
    if (i < n4) out[i] = make_float4(0.f, 0.f, 0.f, 0.f);
}

__global__ __launch_bounds__(256) void scatter_add_kernel(
    const float* __restrict__ x, const void* __restrict__ idx_raw,
    long long E, int n_nodes, const int* __restrict__ is32_flag,
    float* __restrict__ out)
{
    long long tid = (long long)blockIdx.x * blockDim.x + threadIdx.x;
    long long e = tid >> 4;
    int c = (int)(tid & 15);
    if (e >= E) return;
    int is32 = *is32_flag;
    int src = load_idx(idx_raw, e, is32);
    int dst = load_idx(idx_raw, E + e, is32);
    if ((unsigned)src >= (unsigned)n_nodes || (unsigned)dst >= (unsigned)n_nodes) return;
    const float4 v = *reinterpret_cast<const float4*>(x + (long long)src * D_FEAT + c * 4);
    float* p = out + (long long)dst * D_FEAT + c * 4;
    asm volatile("red.global.add.v4.f32 [%0], {%1, %2, %3, %4};"
                 :: "l"(p), "f"(v.x), "f"(v.y), "f"(v.z), "f"(v.w) : "memory");
}

// ---------------- launch -----------------------------------------------------
extern "C" void kernel_launch(void* const* d_in, const int* in_sizes, int n_in,
                              void* d_out, int out_size)
{
    const float* x    = (const float*)d_in[0];
    const void*  up   = d_in[1];
    const void*  down = d_in[2];
    float* out = (float*)d_out;

    const long long E_up   = (long long)in_sizes[1] / 2;
    const long long E_down = (long long)in_sizes[2] / 2;
    const int n_nodes = out_size / D_FEAT;

    int* up_flag;   cudaGetSymbolAddress((void**)&up_flag,   g_up_is_i32);
    int* down_flag; cudaGetSymbolAddress((void**)&down_flag, g_down_is_i32);
    int* cursor;    cudaGetSymbolAddress((void**)&cursor,    g_cursor);
    int* srcids;    cudaGetSymbolAddress((void**)&srcids,    g_srcids);
    __half* xh;     cudaGetSymbolAddress((void**)&xh,        g_xh);
    int* ovf_cnt;   cudaGetSymbolAddress((void**)&ovf_cnt,   g_ovf_cnt);
    int2* ovf;      cudaGetSymbolAddress((void**)&ovf,       g_ovf);

    probe2_kernel<<<2, 256>>>((const unsigned long long*)up,   E_up,   up_flag,
                              (const unsigned long long*)down, E_down, down_flag);

    const int n4 = out_size / 4;

    if (n_nodes <= MAX_NODES) {
        int init_n = n4 > n_nodes ? n4 : n_nodes;
        init_kernel<<<(init_n + 255) / 256, 256>>>((float4*)out, n4, cursor, n_nodes, ovf_cnt);

        long long n_elems = (long long)n_nodes * D_FEAT;
        convert_kernel<<<(int)((n_elems / 8 + 255) / 256), 256>>>(x, xh, n_elems);

        long long units_all = ((E_up + 3) >> 2) + ((E_down + 3) >> 2);
        bucket2_kernel<<<(int)((units_all + 255) / 256), 256>>>(
            up, E_up, down, E_down, n_nodes, up_flag, down_flag,
            cursor, srcids, ovf_cnt, ovf);

        ovf_fixup_kernel<<<16, 256>>>(x, ovf_cnt, ovf, out);

        long long work = (long long)n_nodes * 8;
        gather_h_kernel<<<(int)((work + 255) / 256), 256>>>(xh, cursor, srcids, out, n_nodes);
    } else {
        zero_out_kernel<<<(n4 + 255) / 256, 256>>>((float4*)out, n4);
        long long w1 = E_up * CHUNKS, w2 = E_down * CHUNKS;
        scatter_add_kernel<<<(int)((w1 + 255) / 256), 256>>>(x, up,   E_up,   n_nodes, up_flag,   out);
        scatter_add_kernel<<<(int)((w2 + 255) / 256), 256>>>(x, down, E_down, n_nodes, down_flag, out);
    }
}